// round 6
// baseline (speedup 1.0000x reference)
#include <cuda_runtime.h>
#include <cuda_bf16.h>
#include <stdint.h>
#include <math.h>

// ============================================================================
// ContrastiveDistortion:
//   logits[a,b] = C0 - C1*(P_a.Q_b + s_a + s_b)   (rank-512 SYMMETRIC bilinear)
//   fp32 emulated with bf16x3: P' = [Ph|Ph|Pl] (K=1536), Q' = [Qh|Ql|Qh].
// R6: 256x128 tiles (272 CTAs, j >= 2I), 4-stage cp.async ring, 1 CTA/SM,
// dual row/col fused online LSE with half-block partial slots.
// ============================================================================

namespace {
constexpr int BATCH = 2048;
constexpr int NROW  = 4096;
constexpr int DIM   = 128;
constexpr int KF3   = 1536;           // 3 * 512
constexpr int NBLK  = 32;             // 128-col blocks
constexpr int NCTA  = 272;            // sum_{I=0..15} (32 - 2I)
constexpr int KSTAGES = KF3 / 64;     // 24
constexpr int ROWBYTES = KF3 * 2;     // 3072
constexpr uint32_t STG = 49152u;      // per-stage bytes: A 32KB + B 16KB
constexpr uint32_t BOFF = 32768u;     // B offset within stage

constexpr float C0 = 640.0f;          // D/(2T)
constexpr float C1 = 2.5f;            // 1/(4T)
constexpr float TO_ADD = -1.9538879e-4f;
constexpr float NEG_BIG = -1e30f;
}

__device__ __nv_bfloat16 g_P[(size_t)NROW * KF3];   // 12.6 MB
__device__ __nv_bfloat16 g_Q[(size_t)NROW * KF3];   // 12.6 MB
__device__ float g_s[NROW];
__device__ float g_Lpos[NROW];
__device__ float g_partM[NBLK * NROW];
__device__ float g_partS[NBLK * NROW];

// ---------------------------------------------------------------------------
// helpers
// ---------------------------------------------------------------------------
__device__ __forceinline__ uint32_t smem_u32(const void* p) {
    uint32_t a;
    asm("{ .reg .u64 t; cvta.to.shared.u64 t, %1; cvt.u32.u64 %0, t; }" : "=r"(a) : "l"(p));
    return a;
}
__device__ __forceinline__ void cpasync16(uint32_t dst, const void* src) {
    asm volatile("cp.async.cg.shared.global [%0], [%1], 16;" :: "r"(dst), "l"(src) : "memory");
}
__device__ __forceinline__ void ldsm_x4(uint32_t* r, uint32_t addr) {
    asm volatile("ldmatrix.sync.aligned.m8n8.x4.shared.b16 {%0,%1,%2,%3}, [%4];"
                 : "=r"(r[0]), "=r"(r[1]), "=r"(r[2]), "=r"(r[3]) : "r"(addr));
}
__device__ __forceinline__ void mma16816(float* d, const uint32_t* a, uint32_t b0, uint32_t b1) {
    asm volatile(
        "mma.sync.aligned.m16n8k16.row.col.f32.bf16.bf16.f32 "
        "{%0,%1,%2,%3}, {%4,%5,%6,%7}, {%8,%9}, {%0,%1,%2,%3};"
        : "+f"(d[0]), "+f"(d[1]), "+f"(d[2]), "+f"(d[3])
        : "r"(a[0]), "r"(a[1]), "r"(a[2]), "r"(a[3]), "r"(b0), "r"(b1));
}

// ---------------------------------------------------------------------------
// Kernel 1: build bf16x3 feature rows + row scalars s.
// ---------------------------------------------------------------------------
__global__ void feat_kernel(const float* __restrict__ mu_x,
                            const float* __restrict__ sig_x,
                            const float* __restrict__ mu_p,
                            const float* __restrict__ sig_p) {
    const int t = threadIdx.x;
    const int row = blockIdx.x * 2 + (t >> 6);
    const int d2 = t & 63;

    const float* mu_src = (row < BATCH) ? mu_x + (size_t)row * DIM
                                        : mu_p + (size_t)(row - BATCH) * DIM;
    const float* sg_src = (row < BATCH) ? sig_x + (size_t)row * DIM
                                        : sig_p + (size_t)(row - BATCH) * DIM;
    const float2 mu = *reinterpret_cast<const float2*>(mu_src + 2 * d2);
    const float2 sg = *reinterpret_cast<const float2*>(sg_src + 2 * d2);

    const float var0 = sg.x * sg.x, inv0 = 1.0f / var0;
    const float var1 = sg.y * sg.y, inv1 = 1.0f / var1;
    const float w0 = var0 + mu.x * mu.x, w1 = var1 + mu.y * mu.y;
    const float t0 = mu.x * inv0, t1 = mu.y * inv1;

    const float Pf[4][2] = {{inv0, inv1}, {w0, w1}, {t0, t1}, {mu.x, mu.y}};
    const float Qf[4][2] = {{w0, w1}, {inv0, inv1}, {-2.0f * mu.x, -2.0f * mu.y},
                            {-2.0f * t0, -2.0f * t1}};

    __nv_bfloat16* Prow = g_P + (size_t)row * KF3;
    __nv_bfloat16* Qrow = g_Q + (size_t)row * KF3;

    #pragma unroll
    for (int blk = 0; blk < 4; ++blk) {
        const int k0 = blk * 128 + 2 * d2;
        {
            const float x0 = Pf[blk][0], x1 = Pf[blk][1];
            __nv_bfloat16 h0 = __float2bfloat16(x0), h1 = __float2bfloat16(x1);
            __nv_bfloat16 l0 = __float2bfloat16(x0 - __bfloat162float(h0));
            __nv_bfloat16 l1 = __float2bfloat16(x1 - __bfloat162float(h1));
            __nv_bfloat162 hp = {h0, h1}, lp = {l0, l1};
            const uint32_t hip = *reinterpret_cast<uint32_t*>(&hp);
            const uint32_t lop = *reinterpret_cast<uint32_t*>(&lp);
            *reinterpret_cast<uint32_t*>(Prow +    0 + k0) = hip;
            *reinterpret_cast<uint32_t*>(Prow +  512 + k0) = hip;
            *reinterpret_cast<uint32_t*>(Prow + 1024 + k0) = lop;
        }
        {
            const float x0 = Qf[blk][0], x1 = Qf[blk][1];
            __nv_bfloat16 h0 = __float2bfloat16(x0), h1 = __float2bfloat16(x1);
            __nv_bfloat16 l0 = __float2bfloat16(x0 - __bfloat162float(h0));
            __nv_bfloat16 l1 = __float2bfloat16(x1 - __bfloat162float(h1));
            __nv_bfloat162 hp = {h0, h1}, lp = {l0, l1};
            const uint32_t hip = *reinterpret_cast<uint32_t*>(&hp);
            const uint32_t lop = *reinterpret_cast<uint32_t*>(&lp);
            *reinterpret_cast<uint32_t*>(Qrow +    0 + k0) = hip;
            *reinterpret_cast<uint32_t*>(Qrow +  512 + k0) = lop;
            *reinterpret_cast<uint32_t*>(Qrow + 1024 + k0) = hip;
        }
    }

    float part = t0 * mu.x + t1 * mu.y;
    #pragma unroll
    for (int o = 16; o > 0; o >>= 1) part += __shfl_down_sync(0xffffffffu, part, o);
    __shared__ float ws[4];
    if ((t & 31) == 0) ws[t >> 5] = part;
    __syncthreads();
    if ((t & 63) == 0) g_s[row] = ws[t >> 5] + ws[(t >> 5) + 1];
}

// ---------------------------------------------------------------------------
// Kernel 2: 256x128x1536 bf16 mma.sync GEMM per CTA, fused dual LSE.
// grid = 272, 256 threads (8 warps: wm in {0..3} x wn in {0,1}), 4-stage ring.
// ---------------------------------------------------------------------------
__global__ __launch_bounds__(256, 1) void gemm_kernel() {
    extern __shared__ char smem[];
    __shared__ float srow2[256], scol2[128];        // pre-scaled: C0/2 - C1*s
    __shared__ float redM[256][2], redS[256][2];    // row-side across wn
    __shared__ float redCM[128][4], redCS[128][4];  // col-side across wm

    const int tid = threadIdx.x;
    const int lane = tid & 31;
    const int warp = tid >> 5;
    const int wm = warp >> 1;      // 0..3 (m64 quarter)
    const int wn = warp & 1;       // 0..1 (n64 half)

    // decode bid -> (I, j): rows [256I, 256I+256), col block j in [2I, 31]
    int I = 0, tt = blockIdx.x;
    while (tt >= NBLK - 2 * I) { tt -= NBLK - 2 * I; ++I; }
    const int j = 2 * I + tt;
    const int rowBase = I * 256, colBase = j * 128;
    const int dd = rowBase - colBase;      // cl - rl == dd  -> diagonal
    const int pp = dd + 2048;              // cl - rl == pp  -> positive pair
    const bool jIsLow = (j == 2 * I);      // exclude lower half from row-side

    if (tid < 128) scol2[tid] = 0.5f * C0 - C1 * g_s[colBase + tid];
    srow2[tid]       = 0.5f * C0 - C1 * g_s[rowBase + tid];
    if (tid < 128) srow2[tid + 128] = 0.5f * C0 - C1 * g_s[rowBase + 128 + tid];
    // (above double-writes tid<128 region? no: srow2[tid] covers 0..255 via 256 threads)

    const uint32_t sb = smem_u32(smem);
    const char* gA = (const char*)g_P + (size_t)rowBase * ROWBYTES;
    const char* gB = (const char*)g_Q + (size_t)colBase * ROWBYTES;

    float acc[4][8][4];
    #pragma unroll
    for (int mt = 0; mt < 4; ++mt)
        #pragma unroll
        for (int nt = 0; nt < 8; ++nt)
            #pragma unroll
            for (int e = 0; e < 4; ++e) acc[mt][nt][e] = 0.0f;

    const int l15 = lane & 15, lh = lane >> 4;
    const uint32_t xmask = (uint32_t)(lane & 7) << 4;
    uint32_t rowOffA[4], rowOffB[4], kx[4];
    #pragma unroll
    for (int mt = 0; mt < 4; ++mt) rowOffA[mt] = (uint32_t)(wm * 64 + mt * 16 + l15) * 128u;
    #pragma unroll
    for (int nb = 0; nb < 4; ++nb) rowOffB[nb] = BOFF + (uint32_t)(wn * 64 + nb * 16 + l15) * 128u;
    #pragma unroll
    for (int ks = 0; ks < 4; ++ks) kx[ks] = ((uint32_t)(ks * 32 + lh * 16)) ^ xmask;

    auto load_stage = [&](int kt, int s) {
        const uint32_t base = sb + (uint32_t)s * STG;
        #pragma unroll
        for (int u = 0; u < 8; ++u) {          // A: 256 rows x 128B
            const int id = tid + 256 * u;
            const int r = id >> 3, l8 = id & 7;
            const uint32_t doff = (uint32_t)r * 128u + (uint32_t)((l8 ^ (r & 7)) << 4);
            cpasync16(base + doff, gA + (size_t)r * ROWBYTES + (size_t)kt * 128 + (size_t)l8 * 16);
        }
        #pragma unroll
        for (int u = 0; u < 4; ++u) {          // B: 128 rows x 128B
            const int id = tid + 256 * u;
            const int r = id >> 3, l8 = id & 7;
            const uint32_t doff = BOFF + (uint32_t)r * 128u + (uint32_t)((l8 ^ (r & 7)) << 4);
            cpasync16(base + doff, gB + (size_t)r * ROWBYTES + (size_t)kt * 128 + (size_t)l8 * 16);
        }
        asm volatile("cp.async.commit_group;" ::: "memory");
    };

    load_stage(0, 0);
    load_stage(1, 1);
    load_stage(2, 2);

    for (int kt = 0; kt < KSTAGES; ++kt) {
        const int s = kt & 3;
        if (kt + 2 < KSTAGES) {
            asm volatile("cp.async.wait_group 2;" ::: "memory");
        } else if (kt + 1 < KSTAGES) {
            asm volatile("cp.async.wait_group 1;" ::: "memory");
        } else {
            asm volatile("cp.async.wait_group 0;" ::: "memory");
        }
        __syncthreads();
        if (kt + 3 < KSTAGES) load_stage(kt + 3, (kt + 3) & 3);

        const uint32_t stg = sb + (uint32_t)s * STG;
        #pragma unroll
        for (int ks = 0; ks < 4; ++ks) {
            uint32_t a[4][4], bt[4][4];
            #pragma unroll
            for (int mt = 0; mt < 4; ++mt) ldsm_x4(a[mt], stg + rowOffA[mt] + kx[ks]);
            #pragma unroll
            for (int nb = 0; nb < 4; ++nb) ldsm_x4(bt[nb], stg + rowOffB[nb] + kx[ks]);
            #pragma unroll
            for (int mt = 0; mt < 4; ++mt)
                #pragma unroll
                for (int nt = 0; nt < 8; ++nt)
                    mma16816(acc[mt][nt], a[mt], bt[nt >> 1][nt & 1], bt[nt >> 1][(nt & 1) + 2]);
        }
    }

    // ---- transform acc in place to logits ----
    const int qr = lane >> 2;
    const int qc = (lane & 3) << 1;
    #pragma unroll
    for (int mt = 0; mt < 4; ++mt) {
        #pragma unroll
        for (int nt = 0; nt < 8; ++nt) {
            #pragma unroll
            for (int e = 0; e < 4; ++e) {
                const int rl = wm * 64 + mt * 16 + ((e >> 1) << 3) + qr;
                const int cl = wn * 64 + nt * 8 + qc + (e & 1);
                float val = fmaf(-C1, acc[mt][nt][e], srow2[rl] + scol2[cl]);
                const int drc = cl - rl;
                if (drc == dd) {
                    val = NEG_BIG;
                } else if (drc == pp) {
                    val += TO_ADD;
                    g_Lpos[rowBase + rl] = val;
                    g_Lpos[colBase + cl] = val;
                }
                acc[mt][nt][e] = val;
            }
        }
    }

    // ---- row-side LSE (256 rows; slot j) ----
    #pragma unroll
    for (int mt = 0; mt < 4; ++mt) {
        #pragma unroll
        for (int half = 0; half < 2; ++half) {
            const int rl = wm * 64 + mt * 16 + half * 8 + qr;
            float m = NEG_BIG;
            #pragma unroll
            for (int nt = 0; nt < 8; ++nt)
                #pragma unroll
                for (int jj = 0; jj < 2; ++jj)
                    m = fmaxf(m, acc[mt][nt][half * 2 + jj]);
            float su = 0.0f;
            #pragma unroll
            for (int nt = 0; nt < 8; ++nt)
                #pragma unroll
                for (int jj = 0; jj < 2; ++jj)
                    su += __expf(acc[mt][nt][half * 2 + jj] - m);
            #pragma unroll
            for (int o = 1; o < 4; o <<= 1) {
                const float mo = __shfl_xor_sync(0xffffffffu, m, o);
                const float so = __shfl_xor_sync(0xffffffffu, su, o);
                const float nm = fmaxf(m, mo);
                su = su * __expf(m - nm) + so * __expf(mo - nm);
                m = nm;
            }
            if ((lane & 3) == 0) { redM[rl][wn] = m; redS[rl][wn] = su; }
        }
    }

    // ---- col-side LSE (per 128-row half; slots 2I, 2I+1) ----
    // warp wm covers rows [wm*64, wm*64+64): half = wm>>1; include iff 2I+half < j
    const bool colInclude = (2 * I + (wm >> 1)) < j;
    if (colInclude) {
        #pragma unroll
        for (int nt = 0; nt < 8; ++nt) {
            #pragma unroll
            for (int jj = 0; jj < 2; ++jj) {
                float m = NEG_BIG;
                #pragma unroll
                for (int mt = 0; mt < 4; ++mt)
                    #pragma unroll
                    for (int half = 0; half < 2; ++half)
                        m = fmaxf(m, acc[mt][nt][half * 2 + jj]);
                float su = 0.0f;
                #pragma unroll
                for (int mt = 0; mt < 4; ++mt)
                    #pragma unroll
                    for (int half = 0; half < 2; ++half)
                        su += __expf(acc[mt][nt][half * 2 + jj] - m);
                #pragma unroll
                for (int o = 4; o < 32; o <<= 1) {
                    const float mo = __shfl_xor_sync(0xffffffffu, m, o);
                    const float so = __shfl_xor_sync(0xffffffffu, su, o);
                    const float nm = fmaxf(m, mo);
                    su = su * __expf(m - nm) + so * __expf(mo - nm);
                    m = nm;
                }
                if (lane < 4) {
                    const int cl = wn * 64 + nt * 8 + qc + jj;
                    redCM[cl][wm] = m;
                    redCS[cl][wm] = su;
                }
            }
        }
    }
    __syncthreads();

    // row-side merge across wn -> slot j  (skip lower half when j == 2I)
    if (!(jIsLow && tid >= 128)) {
        const float m0 = redM[tid][0], s0 = redS[tid][0];
        const float m1 = redM[tid][1], s1 = redS[tid][1];
        const float nm = fmaxf(m0, m1);
        g_partM[j * NROW + rowBase + tid] = nm;
        g_partS[j * NROW + rowBase + tid] = s0 * __expf(m0 - nm) + s1 * __expf(m1 - nm);
    }

    // col-side merge: wm {0,1} -> slot 2I; wm {2,3} -> slot 2I+1
    if (tid < 128) {
        if (2 * I < j) {
            const float m0 = redCM[tid][0], s0 = redCS[tid][0];
            const float m1 = redCM[tid][1], s1 = redCS[tid][1];
            const float nm = fmaxf(m0, m1);
            g_partM[(2 * I) * NROW + colBase + tid] = nm;
            g_partS[(2 * I) * NROW + colBase + tid] = s0 * __expf(m0 - nm) + s1 * __expf(m1 - nm);
        }
        if (2 * I + 1 < j) {
            const float m0 = redCM[tid][2], s0 = redCS[tid][2];
            const float m1 = redCM[tid][3], s1 = redCS[tid][3];
            const float nm = fmaxf(m0, m1);
            g_partM[(2 * I + 1) * NROW + colBase + tid] = nm;
            g_partS[(2 * I + 1) * NROW + colBase + tid] = s0 * __expf(m0 - nm) + s1 * __expf(m1 - nm);
        }
    }
}

// ---------------------------------------------------------------------------
// Kernel 3: merge 32 partials per row -> LSE -> mean(lse - Lpos).
// ---------------------------------------------------------------------------
__global__ void reduce_kernel(float* __restrict__ out) {
    __shared__ float red[1024];
    const int tid = threadIdx.x;
    float local = 0.0f;
    for (int row = tid; row < NROW; row += 1024) {
        float M = NEG_BIG, S = 0.0f;
        #pragma unroll
        for (int ch = 0; ch < NBLK; ++ch) {
            const float mj = g_partM[ch * NROW + row];
            const float sj = g_partS[ch * NROW + row];
            const float nm = fmaxf(M, mj);
            S = S * expf(M - nm) + sj * expf(mj - nm);
            M = nm;
        }
        local += (M + logf(S)) - g_Lpos[row];
    }
    red[tid] = local;
    __syncthreads();
    #pragma unroll
    for (int off = 512; off > 0; off >>= 1) {
        if (tid < off) red[tid] += red[tid + off];
        __syncthreads();
    }
    if (tid == 0) out[0] = red[0] / (float)NROW;
}

// ---------------------------------------------------------------------------
extern "C" void kernel_launch(void* const* d_in, const int* in_sizes, int n_in,
                              void* d_out, int out_size) {
    (void)in_sizes; (void)n_in; (void)out_size;
    const float* mu_x  = (const float*)d_in[1];
    const float* sig_x = (const float*)d_in[2];
    const float* mu_p  = (const float*)d_in[3];
    const float* sig_p = (const float*)d_in[4];
    float* out = (float*)d_out;

    static bool attr_set = false;
    if (!attr_set) {
        cudaFuncSetAttribute(gemm_kernel, cudaFuncAttributeMaxDynamicSharedMemorySize, 196608);
        attr_set = true;
    }

    feat_kernel<<<NROW / 2, 128>>>(mu_x, sig_x, mu_p, sig_p);
    gemm_kernel<<<NCTA, 256, 196608>>>();
    reduce_kernel<<<1, 1024>>>(out);
}

// round 7
// speedup vs baseline: 1.3279x; 1.3279x over previous
#include <cuda_runtime.h>
#include <cuda_fp16.h>
#include <stdint.h>
#include <math.h>

// ============================================================================
// ContrastiveDistortion:
//   logits[a,b] = C0 - C1*(P_a.Q_b + s_a + s_b)   (rank-512 SYMMETRIC bilinear)
//   fp32 emulated with fp16x2: P' = [Ph|Pl] (K=1024), Q' = [Qh|Qh].
//   (Ph+Pl).Qh drops only Ph.Ql ~ 2^-12 relative -> rel_err ~1e-4.
// Upper-triangular blocks only (528 CTAs); dual row/col fused online LSE.
// 3-stage cp.async ring, 1 barrier/iter, 2 CTAs/SM.
// ============================================================================

namespace {
constexpr int BATCH = 2048;
constexpr int NROW  = 4096;
constexpr int DIM   = 128;
constexpr int KF2   = 1024;           // 2 * 512
constexpr int NBLK  = 32;             // 4096 / 128
constexpr int NPAIR = NBLK * (NBLK + 1) / 2;   // 528
constexpr int KSTAGES = KF2 / 64;     // 16
constexpr int ROWBYTES = KF2 * 2;     // 2048
constexpr uint32_t STG = 16384u;      // bytes per operand stage

constexpr float C0 = 640.0f;          // D/(2T)
constexpr float C1 = 2.5f;            // 1/(4T)
constexpr float TO_ADD = -1.9538879e-4f;
constexpr float NEG_BIG = -1e30f;
}

__device__ __half g_P[(size_t)NROW * KF2];   // 8.4 MB
__device__ __half g_Q[(size_t)NROW * KF2];   // 8.4 MB
__device__ float g_s[NROW];
__device__ float g_Lpos[NROW];
__device__ float g_partM[NBLK * NROW];
__device__ float g_partS[NBLK * NROW];

// ---------------------------------------------------------------------------
// helpers
// ---------------------------------------------------------------------------
__device__ __forceinline__ uint32_t smem_u32(const void* p) {
    uint32_t a;
    asm("{ .reg .u64 t; cvta.to.shared.u64 t, %1; cvt.u32.u64 %0, t; }" : "=r"(a) : "l"(p));
    return a;
}
__device__ __forceinline__ void cpasync16(uint32_t dst, const void* src) {
    asm volatile("cp.async.cg.shared.global [%0], [%1], 16;" :: "r"(dst), "l"(src) : "memory");
}
__device__ __forceinline__ void ldsm_x4(uint32_t* r, uint32_t addr) {
    asm volatile("ldmatrix.sync.aligned.m8n8.x4.shared.b16 {%0,%1,%2,%3}, [%4];"
                 : "=r"(r[0]), "=r"(r[1]), "=r"(r[2]), "=r"(r[3]) : "r"(addr));
}
__device__ __forceinline__ void mma16816(float* d, const uint32_t* a, uint32_t b0, uint32_t b1) {
    asm volatile(
        "mma.sync.aligned.m16n8k16.row.col.f32.f16.f16.f32 "
        "{%0,%1,%2,%3}, {%4,%5,%6,%7}, {%8,%9}, {%0,%1,%2,%3};"
        : "+f"(d[0]), "+f"(d[1]), "+f"(d[2]), "+f"(d[3])
        : "r"(a[0]), "r"(a[1]), "r"(a[2]), "r"(a[3]), "r"(b0), "r"(b1));
}

// ---------------------------------------------------------------------------
// Kernel 1: build fp16x2 feature rows + row scalars s.
// One block handles 2 rows; thread t: row = 2*bid + (t>>6), dims 2*(t&63)+{0,1}.
// ---------------------------------------------------------------------------
__global__ void feat_kernel(const float* __restrict__ mu_x,
                            const float* __restrict__ sig_x,
                            const float* __restrict__ mu_p,
                            const float* __restrict__ sig_p) {
    const int t = threadIdx.x;
    const int row = blockIdx.x * 2 + (t >> 6);
    const int d2 = t & 63;

    const float* mu_src = (row < BATCH) ? mu_x + (size_t)row * DIM
                                        : mu_p + (size_t)(row - BATCH) * DIM;
    const float* sg_src = (row < BATCH) ? sig_x + (size_t)row * DIM
                                        : sig_p + (size_t)(row - BATCH) * DIM;
    const float2 mu = *reinterpret_cast<const float2*>(mu_src + 2 * d2);
    const float2 sg = *reinterpret_cast<const float2*>(sg_src + 2 * d2);

    const float var0 = sg.x * sg.x, inv0 = 1.0f / var0;
    const float var1 = sg.y * sg.y, inv1 = 1.0f / var1;
    const float w0 = var0 + mu.x * mu.x, w1 = var1 + mu.y * mu.y;
    const float t0 = mu.x * inv0, t1 = mu.y * inv1;

    // P feature blocks {inv, w, t, mu};  Q blocks {w, inv, -2mu, -2t}
    const float Pf[4][2] = {{inv0, inv1}, {w0, w1}, {t0, t1}, {mu.x, mu.y}};
    const float Qf[4][2] = {{w0, w1}, {inv0, inv1}, {-2.0f * mu.x, -2.0f * mu.y},
                            {-2.0f * t0, -2.0f * t1}};

    __half* Prow = g_P + (size_t)row * KF2;
    __half* Qrow = g_Q + (size_t)row * KF2;

    #pragma unroll
    for (int blk = 0; blk < 4; ++blk) {
        const int k0 = blk * 128 + 2 * d2;
        // P: hi | lo
        {
            const float x0 = Pf[blk][0], x1 = Pf[blk][1];
            const __half h0 = __float2half_rn(x0), h1 = __float2half_rn(x1);
            const __half l0 = __float2half_rn(x0 - __half2float(h0));
            const __half l1 = __float2half_rn(x1 - __half2float(h1));
            __half2 hp = {h0, h1}, lp = {l0, l1};
            *reinterpret_cast<uint32_t*>(Prow +   0 + k0) = *reinterpret_cast<uint32_t*>(&hp);
            *reinterpret_cast<uint32_t*>(Prow + 512 + k0) = *reinterpret_cast<uint32_t*>(&lp);
        }
        // Q: hi | hi
        {
            const float x0 = Qf[blk][0], x1 = Qf[blk][1];
            const __half h0 = __float2half_rn(x0), h1 = __float2half_rn(x1);
            __half2 hp = {h0, h1};
            const uint32_t hip = *reinterpret_cast<uint32_t*>(&hp);
            *reinterpret_cast<uint32_t*>(Qrow +   0 + k0) = hip;
            *reinterpret_cast<uint32_t*>(Qrow + 512 + k0) = hip;
        }
    }

    float part = t0 * mu.x + t1 * mu.y;
    #pragma unroll
    for (int o = 16; o > 0; o >>= 1) part += __shfl_down_sync(0xffffffffu, part, o);
    __shared__ float ws[4];
    if ((t & 31) == 0) ws[t >> 5] = part;
    __syncthreads();
    if ((t & 63) == 0) g_s[row] = ws[t >> 5] + ws[(t >> 5) + 1];
}

// ---------------------------------------------------------------------------
// Kernel 2: upper-triangular 128x128x1024 fp16 mma.sync GEMM, fused dual LSE.
// grid = 528 pairs (i<=j), 256 threads, 3-stage cp.async ring, 2 CTAs/SM.
// ---------------------------------------------------------------------------
__global__ __launch_bounds__(256, 2) void gemm_kernel() {
    extern __shared__ char smem[];
    __shared__ float scol[128], srow[128];          // pre-scaled: C0/2 - C1*s
    __shared__ float redM[128][4], redS[128][4];    // row-side across wn
    __shared__ float redCM[128][2], redCS[128][2];  // col-side across wm

    const int tid = threadIdx.x;
    const int lane = tid & 31;
    const int warp = tid >> 5;
    const int wm = warp >> 2;
    const int wn = warp & 3;

    // triangular decode: bid -> (i, j), i <= j
    int i = 0, tt = blockIdx.x;
    while (tt >= NBLK - i) { tt -= NBLK - i; ++i; }
    const int j = i + tt;
    const bool isDiag = (i == j);
    const bool isPair = (j == i + 16);
    const int rowBase = i * 128, colBase = j * 128;

    if (tid < 128) {
        srow[tid] = 0.5f * C0 - C1 * g_s[rowBase + tid];
        scol[tid] = 0.5f * C0 - C1 * g_s[colBase + tid];
    }

    const uint32_t sb = smem_u32(smem);
    const char* gA = (const char*)g_P + (size_t)rowBase * ROWBYTES;
    const char* gB = (const char*)g_Q + (size_t)colBase * ROWBYTES;

    float acc[4][4][4];
    #pragma unroll
    for (int mt = 0; mt < 4; ++mt)
        #pragma unroll
        for (int nt = 0; nt < 4; ++nt)
            #pragma unroll
            for (int e = 0; e < 4; ++e) acc[mt][nt][e] = 0.0f;

    const int l15 = lane & 15, lh = lane >> 4;
    const uint32_t xmask = (uint32_t)(lane & 7) << 4;
    uint32_t rowOffA[4], rowOffB[2], kx[4];
    #pragma unroll
    for (int mt = 0; mt < 4; ++mt) rowOffA[mt] = (uint32_t)(wm * 64 + mt * 16 + l15) * 128u;
    #pragma unroll
    for (int np = 0; np < 2; ++np) rowOffB[np] = (uint32_t)(wn * 32 + np * 16 + l15) * 128u;
    #pragma unroll
    for (int ks = 0; ks < 4; ++ks) kx[ks] = ((uint32_t)(ks * 32 + lh * 16)) ^ xmask;

    // stage layout: A stages [0,3*STG), B stages [3*STG, 6*STG)
    auto load_stage = [&](int kt, int s) {
        const uint32_t aD = sb + (uint32_t)s * STG;
        const uint32_t bD = sb + 3u * STG + (uint32_t)s * STG;
        #pragma unroll
        for (int u = 0; u < 4; ++u) {
            const int id = tid + 256 * u;
            const int r = id >> 3, l8 = id & 7;
            const uint32_t doff = (uint32_t)r * 128u + (uint32_t)((l8 ^ (r & 7)) << 4);
            const size_t soff = (size_t)r * ROWBYTES + (size_t)kt * 128 + (size_t)l8 * 16;
            cpasync16(aD + doff, gA + soff);
            cpasync16(bD + doff, gB + soff);
        }
        asm volatile("cp.async.commit_group;" ::: "memory");
    };

    load_stage(0, 0);
    load_stage(1, 1);

    for (int kt = 0; kt < KSTAGES; ++kt) {
        const int s = kt % 3;
        if (kt + 1 < KSTAGES) {
            asm volatile("cp.async.wait_group 1;" ::: "memory");
        } else {
            asm volatile("cp.async.wait_group 0;" ::: "memory");
        }
        __syncthreads();
        // refill the buffer consumed at iteration kt-1
        if (kt + 2 < KSTAGES) load_stage(kt + 2, (kt + 2) % 3);

        const uint32_t aB = sb + (uint32_t)s * STG;
        const uint32_t bB = sb + 3u * STG + (uint32_t)s * STG;
        #pragma unroll
        for (int ks = 0; ks < 4; ++ks) {
            uint32_t a[4][4], bt[2][4];
            #pragma unroll
            for (int mt = 0; mt < 4; ++mt) ldsm_x4(a[mt], aB + rowOffA[mt] + kx[ks]);
            #pragma unroll
            for (int np = 0; np < 2; ++np) ldsm_x4(bt[np], bB + rowOffB[np] + kx[ks]);
            #pragma unroll
            for (int mt = 0; mt < 4; ++mt)
                #pragma unroll
                for (int nt = 0; nt < 4; ++nt)
                    mma16816(acc[mt][nt], a[mt], bt[nt >> 1][nt & 1], bt[nt >> 1][(nt & 1) + 2]);
        }
    }

    // ---- transform acc in place to logits: val = fma(-C1, acc, sr2+sc2) ----
    const int qr = lane >> 2;
    const int qc = (lane & 3) << 1;
    #pragma unroll
    for (int mt = 0; mt < 4; ++mt) {
        #pragma unroll
        for (int nt = 0; nt < 4; ++nt) {
            #pragma unroll
            for (int e = 0; e < 4; ++e) {
                const int rl = wm * 64 + mt * 16 + ((e >> 1) << 3) + qr;
                const int cl = wn * 32 + nt * 8 + qc + (e & 1);
                float val = fmaf(-C1, acc[mt][nt][e], srow[rl] + scol[cl]);
                if (rl == cl) {
                    if (isDiag) {
                        val = NEG_BIG;
                    } else if (isPair) {
                        val += TO_ADD;
                        g_Lpos[rowBase + rl] = val;
                        g_Lpos[colBase + cl] = val;
                    }
                }
                acc[mt][nt][e] = val;
            }
        }
    }

    // ---- row-side LSE (rows of block i; partial slot j) ----
    #pragma unroll
    for (int mt = 0; mt < 4; ++mt) {
        #pragma unroll
        for (int half = 0; half < 2; ++half) {
            const int rl = wm * 64 + mt * 16 + half * 8 + qr;
            float m = NEG_BIG;
            #pragma unroll
            for (int nt = 0; nt < 4; ++nt)
                #pragma unroll
                for (int jj = 0; jj < 2; ++jj)
                    m = fmaxf(m, acc[mt][nt][half * 2 + jj]);
            float su = 0.0f;
            #pragma unroll
            for (int nt = 0; nt < 4; ++nt)
                #pragma unroll
                for (int jj = 0; jj < 2; ++jj)
                    su += __expf(acc[mt][nt][half * 2 + jj] - m);
            #pragma unroll
            for (int o = 1; o < 4; o <<= 1) {
                const float mo = __shfl_xor_sync(0xffffffffu, m, o);
                const float so = __shfl_xor_sync(0xffffffffu, su, o);
                const float nm = fmaxf(m, mo);
                su = su * __expf(m - nm) + so * __expf(mo - nm);
                m = nm;
            }
            if ((lane & 3) == 0) { redM[rl][wn] = m; redS[rl][wn] = su; }
        }
    }

    // ---- col-side LSE (rows of block j; partial slot i) ----
    if (!isDiag) {
        #pragma unroll
        for (int nt = 0; nt < 4; ++nt) {
            #pragma unroll
            for (int jj = 0; jj < 2; ++jj) {
                float m = NEG_BIG;
                #pragma unroll
                for (int mt = 0; mt < 4; ++mt)
                    #pragma unroll
                    for (int half = 0; half < 2; ++half)
                        m = fmaxf(m, acc[mt][nt][half * 2 + jj]);
                float su = 0.0f;
                #pragma unroll
                for (int mt = 0; mt < 4; ++mt)
                    #pragma unroll
                    for (int half = 0; half < 2; ++half)
                        su += __expf(acc[mt][nt][half * 2 + jj] - m);
                #pragma unroll
                for (int o = 4; o < 32; o <<= 1) {
                    const float mo = __shfl_xor_sync(0xffffffffu, m, o);
                    const float so = __shfl_xor_sync(0xffffffffu, su, o);
                    const float nm = fmaxf(m, mo);
                    su = su * __expf(m - nm) + so * __expf(mo - nm);
                    m = nm;
                }
                if (lane < 4) {
                    const int cl = wn * 32 + nt * 8 + qc + jj;
                    redCM[cl][wm] = m;
                    redCS[cl][wm] = su;
                }
            }
        }
    }
    __syncthreads();

    if (tid < 128) {
        float M = redM[tid][0], S = redS[tid][0];
        #pragma unroll
        for (int q = 1; q < 4; ++q) {
            const float mj = redM[tid][q], sj = redS[tid][q];
            const float nm = fmaxf(M, mj);
            S = S * __expf(M - nm) + sj * __expf(mj - nm);
            M = nm;
        }
        g_partM[j * NROW + rowBase + tid] = M;
        g_partS[j * NROW + rowBase + tid] = S;

        if (!isDiag) {
            float Mc = redCM[tid][0], Sc = redCS[tid][0];
            const float m1 = redCM[tid][1], s1 = redCS[tid][1];
            const float nm = fmaxf(Mc, m1);
            Sc = Sc * __expf(Mc - nm) + s1 * __expf(m1 - nm);
            Mc = nm;
            g_partM[i * NROW + colBase + tid] = Mc;
            g_partS[i * NROW + colBase + tid] = Sc;
        }
    }
}

// ---------------------------------------------------------------------------
// Kernel 3: merge 32 partials per row -> LSE -> mean(lse - Lpos).
// ---------------------------------------------------------------------------
__global__ void reduce_kernel(float* __restrict__ out) {
    __shared__ float red[1024];
    const int tid = threadIdx.x;
    float local = 0.0f;
    for (int row = tid; row < NROW; row += 1024) {
        float M = NEG_BIG, S = 0.0f;
        #pragma unroll
        for (int ch = 0; ch < NBLK; ++ch) {
            const float mj = g_partM[ch * NROW + row];
            const float sj = g_partS[ch * NROW + row];
            const float nm = fmaxf(M, mj);
            S = S * expf(M - nm) + sj * expf(mj - nm);
            M = nm;
        }
        local += (M + logf(S)) - g_Lpos[row];
    }
    red[tid] = local;
    __syncthreads();
    #pragma unroll
    for (int off = 512; off > 0; off >>= 1) {
        if (tid < off) red[tid] += red[tid + off];
        __syncthreads();
    }
    if (tid == 0) out[0] = red[0] / (float)NROW;
}

// ---------------------------------------------------------------------------
extern "C" void kernel_launch(void* const* d_in, const int* in_sizes, int n_in,
                              void* d_out, int out_size) {
    (void)in_sizes; (void)n_in; (void)out_size;
    const float* mu_x  = (const float*)d_in[1];
    const float* sig_x = (const float*)d_in[2];
    const float* mu_p  = (const float*)d_in[3];
    const float* sig_p = (const float*)d_in[4];
    float* out = (float*)d_out;

    static bool attr_set = false;
    if (!attr_set) {
        cudaFuncSetAttribute(gemm_kernel, cudaFuncAttributeMaxDynamicSharedMemorySize, 98304);
        attr_set = true;
    }

    feat_kernel<<<NROW / 2, 128>>>(mu_x, sig_x, mu_p, sig_p);
    gemm_kernel<<<NPAIR, 256, 98304>>>();
    reduce_kernel<<<1, 1024>>>(out);
}

// round 9
// speedup vs baseline: 1.9289x; 1.4526x over previous
#include <cuda_runtime.h>
#include <cuda_fp16.h>
#include <stdint.h>
#include <math.h>

// ============================================================================
// ContrastiveDistortion:
//   logits[a,b] = C0 - C1*(P_a.Q_b + s_a + s_b)   (rank-512 SYMMETRIC bilinear)
//   Single-term fp16: S ~= Ph.Qh (K=512). Truncation errors (2^-12, random
//   sign, both sides) average out at the final scalar (measured ~2.4e-6 per
//   side); the computed matrix stays exactly symmetric.
// Upper-triangular blocks only (528 CTAs); dual row/col fused online LSE.
// 3-stage cp.async ring, 1 barrier/iter, 2 CTAs/SM.
// ============================================================================

namespace {
constexpr int BATCH = 2048;
constexpr int NROW  = 4096;
constexpr int DIM   = 128;
constexpr int KF    = 512;
constexpr int NBLK  = 32;             // 4096 / 128
constexpr int NPAIR = NBLK * (NBLK + 1) / 2;   // 528
constexpr int KSTAGES = KF / 64;      // 8
constexpr int ROWBYTES = KF * 2;      // 1024
constexpr uint32_t STG = 16384u;      // bytes per operand stage

constexpr float C0 = 640.0f;          // D/(2T)
constexpr float C1 = 2.5f;            // 1/(4T)
constexpr float TO_ADD = -1.9538879e-4f;
constexpr float NEG_BIG = -1e30f;
}

__device__ __half g_P[(size_t)NROW * KF];   // 4.2 MB
__device__ __half g_Q[(size_t)NROW * KF];   // 4.2 MB
__device__ float g_s[NROW];
__device__ float g_Lpos[NROW];
__device__ float g_partM[NBLK * NROW];
__device__ float g_partS[NBLK * NROW];

// ---------------------------------------------------------------------------
// helpers
// ---------------------------------------------------------------------------
__device__ __forceinline__ uint32_t smem_u32(const void* p) {
    uint32_t a;
    asm("{ .reg .u64 t; cvta.to.shared.u64 t, %1; cvt.u32.u64 %0, t; }" : "=r"(a) : "l"(p));
    return a;
}
__device__ __forceinline__ void cpasync16(uint32_t dst, const void* src) {
    asm volatile("cp.async.cg.shared.global [%0], [%1], 16;" :: "r"(dst), "l"(src) : "memory");
}
__device__ __forceinline__ void ldsm_x4(uint32_t* r, uint32_t addr) {
    asm volatile("ldmatrix.sync.aligned.m8n8.x4.shared.b16 {%0,%1,%2,%3}, [%4];"
                 : "=r"(r[0]), "=r"(r[1]), "=r"(r[2]), "=r"(r[3]) : "r"(addr));
}
__device__ __forceinline__ void mma16816(float* d, const uint32_t* a, uint32_t b0, uint32_t b1) {
    asm volatile(
        "mma.sync.aligned.m16n8k16.row.col.f32.f16.f16.f32 "
        "{%0,%1,%2,%3}, {%4,%5,%6,%7}, {%8,%9}, {%0,%1,%2,%3};"
        : "+f"(d[0]), "+f"(d[1]), "+f"(d[2]), "+f"(d[3])
        : "r"(a[0]), "r"(a[1]), "r"(a[2]), "r"(a[3]), "r"(b0), "r"(b1));
}

// ---------------------------------------------------------------------------
// Kernel 1: build fp16 feature rows (hi parts only) + row scalars s.
// One block handles 2 rows; thread t: row = 2*bid + (t>>6), dims 2*(t&63)+{0,1}.
// ---------------------------------------------------------------------------
__global__ void feat_kernel(const float* __restrict__ mu_x,
                            const float* __restrict__ sig_x,
                            const float* __restrict__ mu_p,
                            const float* __restrict__ sig_p) {
    const int t = threadIdx.x;
    const int row = blockIdx.x * 2 + (t >> 6);
    const int d2 = t & 63;

    const float* mu_src = (row < BATCH) ? mu_x + (size_t)row * DIM
                                        : mu_p + (size_t)(row - BATCH) * DIM;
    const float* sg_src = (row < BATCH) ? sig_x + (size_t)row * DIM
                                        : sig_p + (size_t)(row - BATCH) * DIM;
    const float2 mu = *reinterpret_cast<const float2*>(mu_src + 2 * d2);
    const float2 sg = *reinterpret_cast<const float2*>(sg_src + 2 * d2);

    const float var0 = sg.x * sg.x, inv0 = 1.0f / var0;
    const float var1 = sg.y * sg.y, inv1 = 1.0f / var1;
    const float w0 = var0 + mu.x * mu.x, w1 = var1 + mu.y * mu.y;
    const float t0 = mu.x * inv0, t1 = mu.y * inv1;

    // P feature blocks {inv, w, t, mu};  Q blocks {w, inv, -2mu, -2t}
    const float Pf[4][2] = {{inv0, inv1}, {w0, w1}, {t0, t1}, {mu.x, mu.y}};
    const float Qf[4][2] = {{w0, w1}, {inv0, inv1}, {-2.0f * mu.x, -2.0f * mu.y},
                            {-2.0f * t0, -2.0f * t1}};

    __half* Prow = g_P + (size_t)row * KF;
    __half* Qrow = g_Q + (size_t)row * KF;

    #pragma unroll
    for (int blk = 0; blk < 4; ++blk) {
        const int k0 = blk * 128 + 2 * d2;
        {
            __half2 hp = {__float2half_rn(Pf[blk][0]), __float2half_rn(Pf[blk][1])};
            *reinterpret_cast<uint32_t*>(Prow + k0) = *reinterpret_cast<uint32_t*>(&hp);
        }
        {
            __half2 hp = {__float2half_rn(Qf[blk][0]), __float2half_rn(Qf[blk][1])};
            *reinterpret_cast<uint32_t*>(Qrow + k0) = *reinterpret_cast<uint32_t*>(&hp);
        }
    }

    float part = t0 * mu.x + t1 * mu.y;
    #pragma unroll
    for (int o = 16; o > 0; o >>= 1) part += __shfl_down_sync(0xffffffffu, part, o);
    __shared__ float ws[4];
    if ((t & 31) == 0) ws[t >> 5] = part;
    __syncthreads();
    if ((t & 63) == 0) g_s[row] = ws[t >> 5] + ws[(t >> 5) + 1];
}

// ---------------------------------------------------------------------------
// Kernel 2: upper-triangular 128x128x512 fp16 mma.sync GEMM, fused dual LSE.
// grid = 528 pairs (i<=j), 256 threads, 3-stage cp.async ring, 2 CTAs/SM.
// ---------------------------------------------------------------------------
__global__ __launch_bounds__(256, 2) void gemm_kernel() {
    extern __shared__ char smem[];
    __shared__ float scol[128], srow[128];          // pre-scaled: C0/2 - C1*s
    __shared__ float redM[128][4], redS[128][4];    // row-side across wn
    __shared__ float redCM[128][2], redCS[128][2];  // col-side across wm

    const int tid = threadIdx.x;
    const int lane = tid & 31;
    const int warp = tid >> 5;
    const int wm = warp >> 2;
    const int wn = warp & 3;

    // triangular decode: bid -> (i, j), i <= j
    int i = 0, tt = blockIdx.x;
    while (tt >= NBLK - i) { tt -= NBLK - i; ++i; }
    const int j = i + tt;
    const bool isDiag = (i == j);
    const bool isPair = (j == i + 16);
    const int rowBase = i * 128, colBase = j * 128;

    if (tid < 128) {
        srow[tid] = 0.5f * C0 - C1 * g_s[rowBase + tid];
        scol[tid] = 0.5f * C0 - C1 * g_s[colBase + tid];
    }

    const uint32_t sb = smem_u32(smem);
    const char* gA = (const char*)g_P + (size_t)rowBase * ROWBYTES;
    const char* gB = (const char*)g_Q + (size_t)colBase * ROWBYTES;

    float acc[4][4][4];
    #pragma unroll
    for (int mt = 0; mt < 4; ++mt)
        #pragma unroll
        for (int nt = 0; nt < 4; ++nt)
            #pragma unroll
            for (int e = 0; e < 4; ++e) acc[mt][nt][e] = 0.0f;

    const int l15 = lane & 15, lh = lane >> 4;
    const uint32_t xmask = (uint32_t)(lane & 7) << 4;
    uint32_t rowOffA[4], rowOffB[2], kx[4];
    #pragma unroll
    for (int mt = 0; mt < 4; ++mt) rowOffA[mt] = (uint32_t)(wm * 64 + mt * 16 + l15) * 128u;
    #pragma unroll
    for (int np = 0; np < 2; ++np) rowOffB[np] = (uint32_t)(wn * 32 + np * 16 + l15) * 128u;
    #pragma unroll
    for (int ks = 0; ks < 4; ++ks) kx[ks] = ((uint32_t)(ks * 32 + lh * 16)) ^ xmask;

    // stage layout: A stages [0,3*STG), B stages [3*STG, 6*STG)
    auto load_stage = [&](int kt, int s) {
        const uint32_t aD = sb + (uint32_t)s * STG;
        const uint32_t bD = sb + 3u * STG + (uint32_t)s * STG;
        #pragma unroll
        for (int u = 0; u < 4; ++u) {
            const int id = tid + 256 * u;
            const int r = id >> 3, l8 = id & 7;
            const uint32_t doff = (uint32_t)r * 128u + (uint32_t)((l8 ^ (r & 7)) << 4);
            const size_t soff = (size_t)r * ROWBYTES + (size_t)kt * 128 + (size_t)l8 * 16;
            cpasync16(aD + doff, gA + soff);
            cpasync16(bD + doff, gB + soff);
        }
        asm volatile("cp.async.commit_group;" ::: "memory");
    };

    load_stage(0, 0);
    load_stage(1, 1);

    for (int kt = 0; kt < KSTAGES; ++kt) {
        const int s = kt % 3;
        if (kt + 1 < KSTAGES) {
            asm volatile("cp.async.wait_group 1;" ::: "memory");
        } else {
            asm volatile("cp.async.wait_group 0;" ::: "memory");
        }
        __syncthreads();
        // refill the buffer consumed at iteration kt-1
        if (kt + 2 < KSTAGES) load_stage(kt + 2, (kt + 2) % 3);

        const uint32_t aB = sb + (uint32_t)s * STG;
        const uint32_t bB = sb + 3u * STG + (uint32_t)s * STG;
        #pragma unroll
        for (int ks = 0; ks < 4; ++ks) {
            uint32_t a[4][4], bt[2][4];
            #pragma unroll
            for (int mt = 0; mt < 4; ++mt) ldsm_x4(a[mt], aB + rowOffA[mt] + kx[ks]);
            #pragma unroll
            for (int np = 0; np < 2; ++np) ldsm_x4(bt[np], bB + rowOffB[np] + kx[ks]);
            #pragma unroll
            for (int mt = 0; mt < 4; ++mt)
                #pragma unroll
                for (int nt = 0; nt < 4; ++nt)
                    mma16816(acc[mt][nt], a[mt], bt[nt >> 1][nt & 1], bt[nt >> 1][(nt & 1) + 2]);
        }
    }

    // ---- transform acc in place to logits: val = fma(-C1, acc, sr2+sc2) ----
    const int qr = lane >> 2;
    const int qc = (lane & 3) << 1;
    #pragma unroll
    for (int mt = 0; mt < 4; ++mt) {
        #pragma unroll
        for (int nt = 0; nt < 4; ++nt) {
            #pragma unroll
            for (int e = 0; e < 4; ++e) {
                const int rl = wm * 64 + mt * 16 + ((e >> 1) << 3) + qr;
                const int cl = wn * 32 + nt * 8 + qc + (e & 1);
                float val = fmaf(-C1, acc[mt][nt][e], srow[rl] + scol[cl]);
                if (rl == cl) {
                    if (isDiag) {
                        val = NEG_BIG;
                    } else if (isPair) {
                        val += TO_ADD;
                        g_Lpos[rowBase + rl] = val;
                        g_Lpos[colBase + cl] = val;
                    }
                }
                acc[mt][nt][e] = val;
            }
        }
    }

    // ---- row-side LSE (rows of block i; partial slot j) ----
    #pragma unroll
    for (int mt = 0; mt < 4; ++mt) {
        #pragma unroll
        for (int half = 0; half < 2; ++half) {
            const int rl = wm * 64 + mt * 16 + half * 8 + qr;
            float m = NEG_BIG;
            #pragma unroll
            for (int nt = 0; nt < 4; ++nt)
                #pragma unroll
                for (int jj = 0; jj < 2; ++jj)
                    m = fmaxf(m, acc[mt][nt][half * 2 + jj]);
            float su = 0.0f;
            #pragma unroll
            for (int nt = 0; nt < 4; ++nt)
                #pragma unroll
                for (int jj = 0; jj < 2; ++jj)
                    su += __expf(acc[mt][nt][half * 2 + jj] - m);
            #pragma unroll
            for (int o = 1; o < 4; o <<= 1) {
                const float mo = __shfl_xor_sync(0xffffffffu, m, o);
                const float so = __shfl_xor_sync(0xffffffffu, su, o);
                const float nm = fmaxf(m, mo);
                su = su * __expf(m - nm) + so * __expf(mo - nm);
                m = nm;
            }
            if ((lane & 3) == 0) { redM[rl][wn] = m; redS[rl][wn] = su; }
        }
    }

    // ---- col-side LSE (rows of block j; partial slot i) ----
    if (!isDiag) {
        #pragma unroll
        for (int nt = 0; nt < 4; ++nt) {
            #pragma unroll
            for (int jj = 0; jj < 2; ++jj) {
                float m = NEG_BIG;
                #pragma unroll
                for (int mt = 0; mt < 4; ++mt)
                    #pragma unroll
                    for (int half = 0; half < 2; ++half)
                        m = fmaxf(m, acc[mt][nt][half * 2 + jj]);
                float su = 0.0f;
                #pragma unroll
                for (int mt = 0; mt < 4; ++mt)
                    #pragma unroll
                    for (int half = 0; half < 2; ++half)
                        su += __expf(acc[mt][nt][half * 2 + jj] - m);
                #pragma unroll
                for (int o = 4; o < 32; o <<= 1) {
                    const float mo = __shfl_xor_sync(0xffffffffu, m, o);
                    const float so = __shfl_xor_sync(0xffffffffu, su, o);
                    const float nm = fmaxf(m, mo);
                    su = su * __expf(m - nm) + so * __expf(mo - nm);
                    m = nm;
                }
                if (lane < 4) {
                    const int cl = wn * 32 + nt * 8 + qc + jj;
                    redCM[cl][wm] = m;
                    redCS[cl][wm] = su;
                }
            }
        }
    }
    __syncthreads();

    if (tid < 128) {
        float M = redM[tid][0], S = redS[tid][0];
        #pragma unroll
        for (int q = 1; q < 4; ++q) {
            const float mj = redM[tid][q], sj = redS[tid][q];
            const float nm = fmaxf(M, mj);
            S = S * __expf(M - nm) + sj * __expf(mj - nm);
            M = nm;
        }
        g_partM[j * NROW + rowBase + tid] = M;
        g_partS[j * NROW + rowBase + tid] = S;

        if (!isDiag) {
            float Mc = redCM[tid][0], Sc = redCS[tid][0];
            const float m1 = redCM[tid][1], s1 = redCS[tid][1];
            const float nm = fmaxf(Mc, m1);
            Sc = Sc * __expf(Mc - nm) + s1 * __expf(m1 - nm);
            Mc = nm;
            g_partM[i * NROW + colBase + tid] = Mc;
            g_partS[i * NROW + colBase + tid] = Sc;
        }
    }
}

// ---------------------------------------------------------------------------
// Kernel 3: merge 32 partials per row -> LSE -> mean(lse - Lpos).
// ---------------------------------------------------------------------------
__global__ void reduce_kernel(float* __restrict__ out) {
    __shared__ float red[1024];
    const int tid = threadIdx.x;
    float local = 0.0f;
    for (int row = tid; row < NROW; row += 1024) {
        float M = NEG_BIG, S = 0.0f;
        #pragma unroll
        for (int ch = 0; ch < NBLK; ++ch) {
            const float mj = g_partM[ch * NROW + row];
            const float sj = g_partS[ch * NROW + row];
            const float nm = fmaxf(M, mj);
            S = S * expf(M - nm) + sj * expf(mj - nm);
            M = nm;
        }
        local += (M + logf(S)) - g_Lpos[row];
    }
    red[tid] = local;
    __syncthreads();
    #pragma unroll
    for (int off = 512; off > 0; off >>= 1) {
        if (tid < off) red[tid] += red[tid + off];
        __syncthreads();
    }
    if (tid == 0) out[0] = red[0] / (float)NROW;
}

// ---------------------------------------------------------------------------
extern "C" void kernel_launch(void* const* d_in, const int* in_sizes, int n_in,
                              void* d_out, int out_size) {
    (void)in_sizes; (void)n_in; (void)out_size;
    const float* mu_x  = (const float*)d_in[1];
    const float* sig_x = (const float*)d_in[2];
    const float* mu_p  = (const float*)d_in[3];
    const float* sig_p = (const float*)d_in[4];
    float* out = (float*)d_out;

    static bool attr_set = false;
    if (!attr_set) {
        cudaFuncSetAttribute(gemm_kernel, cudaFuncAttributeMaxDynamicSharedMemorySize, 98304);
        attr_set = true;
    }

    feat_kernel<<<NROW / 2, 128>>>(mu_x, sig_x, mu_p, sig_p);
    gemm_kernel<<<NPAIR, 256, 98304>>>();
    reduce_kernel<<<1, 1024>>>(out);
}

// round 10
// speedup vs baseline: 2.6504x; 1.3741x over previous
#include <cuda_runtime.h>
#include <cuda_fp16.h>
#include <stdint.h>
#include <math.h>

// ============================================================================
// ContrastiveDistortion:
//   logits[a,b] = C0 - C1*(P_a.Q_b + s_a + s_b)   (rank-512 SYMMETRIC bilinear)
//   Single-term fp16 GEMM (K=512), upper-triangular blocks (528 CTAs), dual
//   row/col fused online LSE. R10: log2-domain softmax (bare EX2), fat feat
//   kernel (512x256, shuffle-only), 32-block reduce with last-block finish.
// ============================================================================

namespace {
constexpr int BATCH = 2048;
constexpr int NROW  = 4096;
constexpr int DIM   = 128;
constexpr int KF    = 512;
constexpr int NBLK  = 32;             // 4096 / 128
constexpr int NPAIR = NBLK * (NBLK + 1) / 2;   // 528
constexpr int KSTAGES = KF / 64;      // 8
constexpr int ROWBYTES = KF * 2;      // 1024
constexpr uint32_t STG = 16384u;      // bytes per operand stage
constexpr int NRED = 32;              // reduce blocks

// log2-domain constants: logits scaled by log2(e)
constexpr float C0L2 = 923.3248262f;          // 640 * log2e
constexpr float C1L2 = 3.606737602f;          // 2.5 * log2e
constexpr float TO_ADD_L2 = -2.8188645e-4f;   // -1.9538879e-4 * log2e
constexpr float LN2 = 0.69314718055994531f;
constexpr float NEG_BIG = -1e30f;
}

__device__ __half g_P[(size_t)NROW * KF];   // 4.2 MB
__device__ __half g_Q[(size_t)NROW * KF];   // 4.2 MB
__device__ float g_s[NROW];
__device__ float g_Lpos[NROW];              // log2-domain
__device__ float g_partM[NBLK * NROW];      // log2-domain
__device__ float g_partS[NBLK * NROW];
__device__ float g_bsum[NRED];
__device__ int   g_cnt;                     // zero-init; reset by last block

// ---------------------------------------------------------------------------
// helpers
// ---------------------------------------------------------------------------
__device__ __forceinline__ uint32_t smem_u32(const void* p) {
    uint32_t a;
    asm("{ .reg .u64 t; cvta.to.shared.u64 t, %1; cvt.u32.u64 %0, t; }" : "=r"(a) : "l"(p));
    return a;
}
__device__ __forceinline__ float ex2f(float x) {
    float r;
    asm("ex2.approx.ftz.f32 %0, %1;" : "=f"(r) : "f"(x));
    return r;
}
__device__ __forceinline__ void cpasync16(uint32_t dst, const void* src) {
    asm volatile("cp.async.cg.shared.global [%0], [%1], 16;" :: "r"(dst), "l"(src) : "memory");
}
__device__ __forceinline__ void ldsm_x4(uint32_t* r, uint32_t addr) {
    asm volatile("ldmatrix.sync.aligned.m8n8.x4.shared.b16 {%0,%1,%2,%3}, [%4];"
                 : "=r"(r[0]), "=r"(r[1]), "=r"(r[2]), "=r"(r[3]) : "r"(addr));
}
__device__ __forceinline__ void mma16816(float* d, const uint32_t* a, uint32_t b0, uint32_t b1) {
    asm volatile(
        "mma.sync.aligned.m16n8k16.row.col.f32.f16.f16.f32 "
        "{%0,%1,%2,%3}, {%4,%5,%6,%7}, {%8,%9}, {%0,%1,%2,%3};"
        : "+f"(d[0]), "+f"(d[1]), "+f"(d[2]), "+f"(d[3])
        : "r"(a[0]), "r"(a[1]), "r"(a[2]), "r"(a[3]), "r"(b0), "r"(b1));
}

// ---------------------------------------------------------------------------
// Kernel 1: build fp16 feature rows + row scalars s.
// 512 blocks x 256 threads; 8 rows/block (32 threads per row, float4 dims).
// ---------------------------------------------------------------------------
__global__ __launch_bounds__(256) void feat_kernel(
        const float* __restrict__ mu_x,  const float* __restrict__ sig_x,
        const float* __restrict__ mu_p,  const float* __restrict__ sig_p) {
    const int t = threadIdx.x;
    const int lane = t & 31;
    const int row = blockIdx.x * 8 + (t >> 5);
    const int d4 = lane * 4;

    const float* mu_src = (row < BATCH) ? mu_x + (size_t)row * DIM
                                        : mu_p + (size_t)(row - BATCH) * DIM;
    const float* sg_src = (row < BATCH) ? sig_x + (size_t)row * DIM
                                        : sig_p + (size_t)(row - BATCH) * DIM;
    const float4 mu = *reinterpret_cast<const float4*>(mu_src + d4);
    const float4 sg = *reinterpret_cast<const float4*>(sg_src + d4);

    float mv[4] = {mu.x, mu.y, mu.z, mu.w};
    float inv[4], w[4], tq[4];
    {
        const float sv[4] = {sg.x, sg.y, sg.z, sg.w};
        #pragma unroll
        for (int e = 0; e < 4; ++e) {
            const float var = sv[e] * sv[e];
            inv[e] = 1.0f / var;
            w[e]   = var + mv[e] * mv[e];
            tq[e]  = mv[e] * inv[e];
        }
    }

    __half* Prow = g_P + (size_t)row * KF;
    __half* Qrow = g_Q + (size_t)row * KF;

    auto pack4 = [](const float* v, float sc) -> uint2 {
        __half2 a = {__float2half_rn(v[0] * sc), __float2half_rn(v[1] * sc)};
        __half2 b = {__float2half_rn(v[2] * sc), __float2half_rn(v[3] * sc)};
        uint2 u;
        u.x = *reinterpret_cast<uint32_t*>(&a);
        u.y = *reinterpret_cast<uint32_t*>(&b);
        return u;
    };

    // P blocks {inv, w, tq, mu};  Q blocks {w, inv, -2mu, -2tq}
    *reinterpret_cast<uint2*>(Prow +   0 + d4) = pack4(inv, 1.0f);
    *reinterpret_cast<uint2*>(Prow + 128 + d4) = pack4(w,   1.0f);
    *reinterpret_cast<uint2*>(Prow + 256 + d4) = pack4(tq,  1.0f);
    *reinterpret_cast<uint2*>(Prow + 384 + d4) = pack4(mv,  1.0f);
    *reinterpret_cast<uint2*>(Qrow +   0 + d4) = pack4(w,   1.0f);
    *reinterpret_cast<uint2*>(Qrow + 128 + d4) = pack4(inv, 1.0f);
    *reinterpret_cast<uint2*>(Qrow + 256 + d4) = pack4(mv, -2.0f);
    *reinterpret_cast<uint2*>(Qrow + 384 + d4) = pack4(tq, -2.0f);

    // s = sum_d mu^2 / var  (full 32-lane shuffle reduce)
    float part = tq[0] * mv[0] + tq[1] * mv[1] + tq[2] * mv[2] + tq[3] * mv[3];
    #pragma unroll
    for (int o = 16; o > 0; o >>= 1) part += __shfl_down_sync(0xffffffffu, part, o);
    if (lane == 0) g_s[row] = part;
}

// ---------------------------------------------------------------------------
// Kernel 2: upper-triangular 128x128x512 fp16 mma.sync GEMM, fused dual LSE.
// grid = 528 pairs (i<=j), 256 threads, 3-stage cp.async ring, 2 CTAs/SM.
// All logits in log2 domain -> bare EX2 for every exponential.
// ---------------------------------------------------------------------------
__global__ __launch_bounds__(256, 2) void gemm_kernel() {
    extern __shared__ char smem[];
    __shared__ float scol[128], srow[128];          // pre-scaled: C0L2/2 - C1L2*s
    __shared__ float redM[128][4], redS[128][4];    // row-side across wn
    __shared__ float redCM[128][2], redCS[128][2];  // col-side across wm

    const int tid = threadIdx.x;
    const int lane = tid & 31;
    const int warp = tid >> 5;
    const int wm = warp >> 2;
    const int wn = warp & 3;

    // triangular decode: bid -> (i, j), i <= j
    int i = 0, tt = blockIdx.x;
    while (tt >= NBLK - i) { tt -= NBLK - i; ++i; }
    const int j = i + tt;
    const bool isDiag = (i == j);
    const bool isPair = (j == i + 16);
    const int rowBase = i * 128, colBase = j * 128;

    if (tid < 128) {
        srow[tid] = 0.5f * C0L2 - C1L2 * g_s[rowBase + tid];
        scol[tid] = 0.5f * C0L2 - C1L2 * g_s[colBase + tid];
    }

    const uint32_t sb = smem_u32(smem);
    const char* gA = (const char*)g_P + (size_t)rowBase * ROWBYTES;
    const char* gB = (const char*)g_Q + (size_t)colBase * ROWBYTES;

    float acc[4][4][4];
    #pragma unroll
    for (int mt = 0; mt < 4; ++mt)
        #pragma unroll
        for (int nt = 0; nt < 4; ++nt)
            #pragma unroll
            for (int e = 0; e < 4; ++e) acc[mt][nt][e] = 0.0f;

    const int l15 = lane & 15, lh = lane >> 4;
    const uint32_t xmask = (uint32_t)(lane & 7) << 4;
    uint32_t rowOffA[4], rowOffB[2], kx[4];
    #pragma unroll
    for (int mt = 0; mt < 4; ++mt) rowOffA[mt] = (uint32_t)(wm * 64 + mt * 16 + l15) * 128u;
    #pragma unroll
    for (int np = 0; np < 2; ++np) rowOffB[np] = (uint32_t)(wn * 32 + np * 16 + l15) * 128u;
    #pragma unroll
    for (int ks = 0; ks < 4; ++ks) kx[ks] = ((uint32_t)(ks * 32 + lh * 16)) ^ xmask;

    // stage layout: A stages [0,3*STG), B stages [3*STG, 6*STG)
    auto load_stage = [&](int kt, int s) {
        const uint32_t aD = sb + (uint32_t)s * STG;
        const uint32_t bD = sb + 3u * STG + (uint32_t)s * STG;
        #pragma unroll
        for (int u = 0; u < 4; ++u) {
            const int id = tid + 256 * u;
            const int r = id >> 3, l8 = id & 7;
            const uint32_t doff = (uint32_t)r * 128u + (uint32_t)((l8 ^ (r & 7)) << 4);
            const size_t soff = (size_t)r * ROWBYTES + (size_t)kt * 128 + (size_t)l8 * 16;
            cpasync16(aD + doff, gA + soff);
            cpasync16(bD + doff, gB + soff);
        }
        asm volatile("cp.async.commit_group;" ::: "memory");
    };

    load_stage(0, 0);
    load_stage(1, 1);

    for (int kt = 0; kt < KSTAGES; ++kt) {
        const int s = kt % 3;
        if (kt + 1 < KSTAGES) {
            asm volatile("cp.async.wait_group 1;" ::: "memory");
        } else {
            asm volatile("cp.async.wait_group 0;" ::: "memory");
        }
        __syncthreads();
        if (kt + 2 < KSTAGES) load_stage(kt + 2, (kt + 2) % 3);

        const uint32_t aB = sb + (uint32_t)s * STG;
        const uint32_t bB = sb + 3u * STG + (uint32_t)s * STG;
        #pragma unroll
        for (int ks = 0; ks < 4; ++ks) {
            uint32_t a[4][4], bt[2][4];
            #pragma unroll
            for (int mt = 0; mt < 4; ++mt) ldsm_x4(a[mt], aB + rowOffA[mt] + kx[ks]);
            #pragma unroll
            for (int np = 0; np < 2; ++np) ldsm_x4(bt[np], bB + rowOffB[np] + kx[ks]);
            #pragma unroll
            for (int mt = 0; mt < 4; ++mt)
                #pragma unroll
                for (int nt = 0; nt < 4; ++nt)
                    mma16816(acc[mt][nt], a[mt], bt[nt >> 1][nt & 1], bt[nt >> 1][(nt & 1) + 2]);
        }
    }

    // ---- transform acc to log2-domain logits ----
    const int qr = lane >> 2;
    const int qc = (lane & 3) << 1;
    #pragma unroll
    for (int mt = 0; mt < 4; ++mt) {
        #pragma unroll
        for (int nt = 0; nt < 4; ++nt) {
            #pragma unroll
            for (int e = 0; e < 4; ++e) {
                const int rl = wm * 64 + mt * 16 + ((e >> 1) << 3) + qr;
                const int cl = wn * 32 + nt * 8 + qc + (e & 1);
                float val = fmaf(-C1L2, acc[mt][nt][e], srow[rl] + scol[cl]);
                if (rl == cl) {
                    if (isDiag) {
                        val = NEG_BIG;
                    } else if (isPair) {
                        val += TO_ADD_L2;
                        g_Lpos[rowBase + rl] = val;
                        g_Lpos[colBase + cl] = val;
                    }
                }
                acc[mt][nt][e] = val;
            }
        }
    }

    // ---- row-side LSE (rows of block i; partial slot j) ----
    #pragma unroll
    for (int mt = 0; mt < 4; ++mt) {
        #pragma unroll
        for (int half = 0; half < 2; ++half) {
            const int rl = wm * 64 + mt * 16 + half * 8 + qr;
            float m = NEG_BIG;
            #pragma unroll
            for (int nt = 0; nt < 4; ++nt)
                #pragma unroll
                for (int jj = 0; jj < 2; ++jj)
                    m = fmaxf(m, acc[mt][nt][half * 2 + jj]);
            float su = 0.0f;
            #pragma unroll
            for (int nt = 0; nt < 4; ++nt)
                #pragma unroll
                for (int jj = 0; jj < 2; ++jj)
                    su += ex2f(acc[mt][nt][half * 2 + jj] - m);
            #pragma unroll
            for (int o = 1; o < 4; o <<= 1) {
                const float mo = __shfl_xor_sync(0xffffffffu, m, o);
                const float so = __shfl_xor_sync(0xffffffffu, su, o);
                const float nm = fmaxf(m, mo);
                su = su * ex2f(m - nm) + so * ex2f(mo - nm);
                m = nm;
            }
            if ((lane & 3) == 0) { redM[rl][wn] = m; redS[rl][wn] = su; }
        }
    }

    // ---- col-side LSE (rows of block j; partial slot i) ----
    if (!isDiag) {
        #pragma unroll
        for (int nt = 0; nt < 4; ++nt) {
            #pragma unroll
            for (int jj = 0; jj < 2; ++jj) {
                float m = NEG_BIG;
                #pragma unroll
                for (int mt = 0; mt < 4; ++mt)
                    #pragma unroll
                    for (int half = 0; half < 2; ++half)
                        m = fmaxf(m, acc[mt][nt][half * 2 + jj]);
                float su = 0.0f;
                #pragma unroll
                for (int mt = 0; mt < 4; ++mt)
                    #pragma unroll
                    for (int half = 0; half < 2; ++half)
                        su += ex2f(acc[mt][nt][half * 2 + jj] - m);
                #pragma unroll
                for (int o = 4; o < 32; o <<= 1) {
                    const float mo = __shfl_xor_sync(0xffffffffu, m, o);
                    const float so = __shfl_xor_sync(0xffffffffu, su, o);
                    const float nm = fmaxf(m, mo);
                    su = su * ex2f(m - nm) + so * ex2f(mo - nm);
                    m = nm;
                }
                if (lane < 4) {
                    const int cl = wn * 32 + nt * 8 + qc + jj;
                    redCM[cl][wm] = m;
                    redCS[cl][wm] = su;
                }
            }
        }
    }
    __syncthreads();

    if (tid < 128) {
        float M = redM[tid][0], S = redS[tid][0];
        #pragma unroll
        for (int q = 1; q < 4; ++q) {
            const float mj = redM[tid][q], sj = redS[tid][q];
            const float nm = fmaxf(M, mj);
            S = S * ex2f(M - nm) + sj * ex2f(mj - nm);
            M = nm;
        }
        g_partM[j * NROW + rowBase + tid] = M;
        g_partS[j * NROW + rowBase + tid] = S;

        if (!isDiag) {
            float Mc = redCM[tid][0], Sc = redCS[tid][0];
            const float m1 = redCM[tid][1], s1 = redCS[tid][1];
            const float nm = fmaxf(Mc, m1);
            Sc = Sc * ex2f(Mc - nm) + s1 * ex2f(m1 - nm);
            g_partM[i * NROW + colBase + tid] = nm;
            g_partS[i * NROW + colBase + tid] = Sc;
        }
    }
}

// ---------------------------------------------------------------------------
// Kernel 3: 32 blocks x 128 threads; per-row LSE merge (max pass + sum pass),
// block partial sums, deterministic last-block finish.
// ---------------------------------------------------------------------------
__global__ __launch_bounds__(128) void reduce_kernel(float* __restrict__ out) {
    __shared__ float red[128];
    const int tid = threadIdx.x;
    const int row = blockIdx.x * 128 + tid;

    float mv[NBLK];
    float M = NEG_BIG;
    #pragma unroll
    for (int ch = 0; ch < NBLK; ++ch) {
        mv[ch] = g_partM[ch * NROW + row];
        M = fmaxf(M, mv[ch]);
    }
    float S = 0.0f;
    #pragma unroll
    for (int ch = 0; ch < NBLK; ++ch)
        S += g_partS[ch * NROW + row] * ex2f(mv[ch] - M);

    red[tid] = (M + __log2f(S)) - g_Lpos[row];
    __syncthreads();
    #pragma unroll
    for (int off = 64; off > 0; off >>= 1) {
        if (tid < off) red[tid] += red[tid + off];
        __syncthreads();
    }
    if (tid == 0) {
        g_bsum[blockIdx.x] = red[0];
        __threadfence();
        const int done = atomicAdd(&g_cnt, 1);
        if (done == NRED - 1) {
            float tot = 0.0f;
            #pragma unroll
            for (int k = 0; k < NRED; ++k) tot += g_bsum[k];
            out[0] = tot * LN2 / (float)NROW;
            g_cnt = 0;   // reset for next graph replay
        }
    }
}

// ---------------------------------------------------------------------------
extern "C" void kernel_launch(void* const* d_in, const int* in_sizes, int n_in,
                              void* d_out, int out_size) {
    (void)in_sizes; (void)n_in; (void)out_size;
    const float* mu_x  = (const float*)d_in[1];
    const float* sig_x = (const float*)d_in[2];
    const float* mu_p  = (const float*)d_in[3];
    const float* sig_p = (const float*)d_in[4];
    float* out = (float*)d_out;

    static bool attr_set = false;
    if (!attr_set) {
        cudaFuncSetAttribute(gemm_kernel, cudaFuncAttributeMaxDynamicSharedMemorySize, 98304);
        attr_set = true;
    }

    feat_kernel<<<NROW / 8, 256>>>(mu_x, sig_x, mu_p, sig_p);
    gemm_kernel<<<NPAIR, 256, 98304>>>();
    reduce_kernel<<<NRED, 128>>>(out);
}